// round 5
// baseline (speedup 1.0000x reference)
#include <cuda_runtime.h>
#include <cstdint>

// ---------------------------------------------------------------------------
// TopK AutoEncoder: recon = (topk(A @ W_enc)) @ W_dec + b_pre
// Outputs (tuple order): recon [B,D], acts [B,H], z [B,H]
// B=4096, D=768, H=24576, k=32
// Encode GEMM: mma.sync m16n8k8 tf32, 3xTF32 split (hh+hl+lh) -> ~fp32 accuracy.
// (tcgen05 is unavailable: harness targets sm_103 without the 'a' feature.)
// Top-k: radix select + fp64 boundary-band refinement (exact selection).
// ---------------------------------------------------------------------------

__device__ __forceinline__ float tf32r(float x) {
    float y;
    asm("cvt.rna.tf32.f32 %0, %1;" : "=f"(y) : "f"(x));
    return y;
}
__device__ __forceinline__ uint32_t smem_u32(const void* p) {
    uint32_t a;
    asm("{ .reg .u64 t; cvta.to.shared.u64 t, %1; cvt.u32.u64 %0, t; }"
        : "=r"(a) : "l"(p));
    return a;
}
__device__ __forceinline__ void cpa16(uint32_t dst, const void* src) {
    asm volatile("cp.async.cg.shared.global [%0], [%1], 16;"
                 :: "r"(dst), "l"(src));
}
__device__ __forceinline__ void mma8(float* c, const uint32_t* a, const uint32_t* b) {
    asm volatile(
        "mma.sync.aligned.m16n8k8.row.col.f32.tf32.tf32.f32 "
        "{%0,%1,%2,%3}, {%4,%5,%6,%7}, {%8,%9}, {%0,%1,%2,%3};"
        : "+f"(c[0]), "+f"(c[1]), "+f"(c[2]), "+f"(c[3])
        : "r"(a[0]), "r"(a[1]), "r"(a[2]), "r"(a[3]), "r"(b[0]), "r"(b[1]));
}

// ===================== Kernel 1: encode GEMM (mma.sync 3xTF32) ==============
// Block tile 128(m) x 256(n), Kc=16 per chunk, 48 chunks over D=768.
// 8 warps as 2(m) x 4(n); warp tile 64x64 -> 4 m-tiles x 8 n-tiles of 16x8.
#define BM 128
#define BN 256
#define NCH 48
#define APITCH 20     /* floats per A smem row (16 k + pad) */
#define WPITCH 264    /* floats per W smem row (256 n + pad) */
#define AS_FL (128 * APITCH)     /* 2560 */
#define WS_FL (16 * WPITCH)      /* 4224 */
#define GEMM_SMEM ((2 * AS_FL + 2 * WS_FL) * 4)

__global__ void __launch_bounds__(256, 1)
encode_gemm_mma(const float* __restrict__ A,
                const float* __restrict__ W,
                const float* __restrict__ bpre,
                float* __restrict__ acts,
                int D, int H)
{
    extern __shared__ float sm[];
    float* Asb[2] = { sm, sm + AS_FL };
    float* Wsb[2] = { sm + 2 * AS_FL, sm + 2 * AS_FL + WS_FL };

    const int tid = threadIdx.x;
    const int w = tid >> 5;
    const int lane = tid & 31;
    const int lr = lane >> 2;      // group id (0..7)
    const int lc = lane & 3;       // thread-in-group (0..3)
    const int wm = w >> 2;         // 0..1
    const int wn = w & 3;          // 0..3
    const int m0 = blockIdx.x * BM;
    const int n0 = blockIdx.y * BN;

    float C[4][8][4];
#pragma unroll
    for (int mt = 0; mt < 4; mt++)
#pragma unroll
        for (int nt = 0; nt < 8; nt++)
#pragma unroll
            for (int r = 0; r < 4; r++) C[mt][nt][r] = 0.0f;

    // ---- prologue: chunk 0
    {
        // W chunk 0 via cp.async (raw fp32)
#pragma unroll
        for (int i = 0; i < 4; i++) {
            int idx = tid + i * 256;
            int kr = idx >> 6;
            int nq = (idx & 63) * 4;
            cpa16(smem_u32(&Wsb[0][kr * WPITCH + nq]),
                  W + (size_t)kr * H + n0 + nq);
        }
        asm volatile("cp.async.commit_group;" ::: "memory");
        // A chunk 0 direct
#pragma unroll
        for (int i = 0; i < 2; i++) {
            int idx = tid + i * 256;
            int row = idx >> 2;
            int kq = (idx & 3) * 4;
            float4 av = *(const float4*)(A + (size_t)(m0 + row) * D + kq);
            float4 bv = *(const float4*)(bpre + kq);
            av.x -= bv.x; av.y -= bv.y; av.z -= bv.z; av.w -= bv.w;
            *(float4*)&Asb[0][row * APITCH + kq] = av;
        }
    }

#pragma unroll 1
    for (int c = 0; c < NCH; c++) {
        const int buf = c & 1;
        const int k0n = (c + 1) * 16;
        const bool more = (c + 1 < NCH);

        asm volatile("cp.async.wait_group 0;" ::: "memory");
        __syncthreads();

        float4 apre[2];
        if (more) {
            // prefetch A(c+1) to regs (latency hidden by compute below)
#pragma unroll
            for (int i = 0; i < 2; i++) {
                int idx = tid + i * 256;
                int row = idx >> 2;
                int kq = (idx & 3) * 4;
                float4 av = *(const float4*)(A + (size_t)(m0 + row) * D + k0n + kq);
                float4 bv = *(const float4*)(bpre + k0n + kq);
                av.x -= bv.x; av.y -= bv.y; av.z -= bv.z; av.w -= bv.w;
                apre[i] = av;
            }
            // W(c+1) cp.async into other buffer
#pragma unroll
            for (int i = 0; i < 4; i++) {
                int idx = tid + i * 256;
                int kr = idx >> 6;
                int nq = (idx & 63) * 4;
                cpa16(smem_u32(&Wsb[buf ^ 1][kr * WPITCH + nq]),
                      W + (size_t)(k0n + kr) * H + n0 + nq);
            }
            asm volatile("cp.async.commit_group;" ::: "memory");
        }

        // ---- compute chunk c (2 k-steps of 8)
        const float* Ap = Asb[buf];
        const float* Wp = Wsb[buf];
#pragma unroll
        for (int ks = 0; ks < 2; ks++) {
            const int kc = ks * 8;
            // raw fragments
            float rA[4][4], rB[8][2];
            const float* ap = Ap + (wm * 64 + lr) * APITCH + kc + lc;
#pragma unroll
            for (int mt = 0; mt < 4; mt++) {
                rA[mt][0] = ap[mt * 16 * APITCH];
                rA[mt][1] = ap[mt * 16 * APITCH + 8 * APITCH];
                rA[mt][2] = ap[mt * 16 * APITCH + 4];
                rA[mt][3] = ap[mt * 16 * APITCH + 8 * APITCH + 4];
            }
            const float* bp = Wp + (kc + lc) * WPITCH + wn * 64 + lr;
#pragma unroll
            for (int nt = 0; nt < 8; nt++) {
                rB[nt][0] = bp[nt * 8];
                rB[nt][1] = bp[nt * 8 + 4 * WPITCH];
            }
            // hi parts
            uint32_t Ah[4][4], Bh[8][2];
            float Ahf[4][4], Bhf[8][2];
#pragma unroll
            for (int mt = 0; mt < 4; mt++)
#pragma unroll
                for (int r = 0; r < 4; r++) {
                    Ahf[mt][r] = tf32r(rA[mt][r]);
                    Ah[mt][r] = __float_as_uint(Ahf[mt][r]);
                }
#pragma unroll
            for (int nt = 0; nt < 8; nt++)
#pragma unroll
                for (int r = 0; r < 2; r++) {
                    Bhf[nt][r] = tf32r(rB[nt][r]);
                    Bh[nt][r] = __float_as_uint(Bhf[nt][r]);
                }
            // hh
#pragma unroll
            for (int mt = 0; mt < 4; mt++)
#pragma unroll
                for (int nt = 0; nt < 8; nt++)
                    mma8(C[mt][nt], Ah[mt], Bh[nt]);
            // lh: Alo x Bhi  (Alo overwrites rA)
            uint32_t Al[4][4];
#pragma unroll
            for (int mt = 0; mt < 4; mt++)
#pragma unroll
                for (int r = 0; r < 4; r++)
                    Al[mt][r] = __float_as_uint(tf32r(rA[mt][r] - Ahf[mt][r]));
#pragma unroll
            for (int mt = 0; mt < 4; mt++)
#pragma unroll
                for (int nt = 0; nt < 8; nt++)
                    mma8(C[mt][nt], Al[mt], Bh[nt]);
            // hl: Ahi x Blo
            uint32_t Bl[8][2];
#pragma unroll
            for (int nt = 0; nt < 8; nt++)
#pragma unroll
                for (int r = 0; r < 2; r++)
                    Bl[nt][r] = __float_as_uint(tf32r(rB[nt][r] - Bhf[nt][r]));
#pragma unroll
            for (int mt = 0; mt < 4; mt++)
#pragma unroll
                for (int nt = 0; nt < 8; nt++)
                    mma8(C[mt][nt], Ah[mt], Bl[nt]);
        }

        if (more) {
            // store prefetched A into other buffer
#pragma unroll
            for (int i = 0; i < 2; i++) {
                int idx = tid + i * 256;
                int row = idx >> 2;
                int kq = (idx & 3) * 4;
                *(float4*)&Asb[buf ^ 1][row * APITCH + kq] = apre[i];
            }
        }
    }

    // ---- epilogue
#pragma unroll
    for (int mt = 0; mt < 4; mt++) {
        const int r0 = m0 + wm * 64 + mt * 16 + lr;
#pragma unroll
        for (int nt = 0; nt < 8; nt++) {
            const int cc = n0 + wn * 64 + nt * 8 + 2 * lc;
            *(float2*)(acts + (size_t)r0 * H + cc) =
                make_float2(C[mt][nt][0], C[mt][nt][1]);
            *(float2*)(acts + (size_t)(r0 + 8) * H + cc) =
                make_float2(C[mt][nt][2], C[mt][nt][3]);
        }
    }
}

// ============ Kernel 2: top-k (fp64-refined boundary) + z + decode ==========
__device__ __forceinline__ unsigned int f2key(float f) {
    unsigned int u = __float_as_uint(f);
    return (u & 0x80000000u) ? ~u : (u | 0x80000000u);
}
__device__ __forceinline__ float key2f(unsigned int u) {
    unsigned int b = (u & 0x80000000u) ? (u ^ 0x80000000u) : ~u;
    return __uint_as_float(b);
}

#define TOPK_THREADS 256
#define SEL_CAP 64
#define BAND_CAP 64
#define BAND_EPS 2e-3f

__global__ void __launch_bounds__(TOPK_THREADS)
topk_decode_kernel(const float* __restrict__ acts,
                   const float* __restrict__ A,
                   const float* __restrict__ Wenc,
                   const float* __restrict__ Wdec,
                   const float* __restrict__ bpre,
                   const int* __restrict__ kptr,
                   float* __restrict__ z,
                   float* __restrict__ recon,
                   int H, int D)
{
    extern __shared__ unsigned int su[];   // H keys
    __shared__ unsigned int hist[256];
    __shared__ unsigned int sh_prefix, sh_mask;
    __shared__ int sh_remaining;
    __shared__ int ncore, nband;
    __shared__ int   tki[SEL_CAP];
    __shared__ float tkv[SEL_CAP];
    __shared__ int    bidx[BAND_CAP];
    __shared__ float  bvalf[BAND_CAP];
    __shared__ double bvald[BAND_CAP];
    __shared__ unsigned char bsel[BAND_CAP];
    __shared__ int ntot;

    const int row = blockIdx.x;
    const int tid = threadIdx.x;
    const int lane = tid & 31;
    const int wid = tid >> 5;
    const int k = *kptr;
    const float* arow = acts + (size_t)row * H;

    for (int j = tid; j < H; j += TOPK_THREADS)
        su[j] = f2key(arow[j]);

    if (tid == 0) {
        sh_prefix = 0u; sh_mask = 0u; sh_remaining = k;
        ncore = 0; nband = 0; ntot = 0;
    }
    __syncthreads();

#pragma unroll
    for (int shift = 24; shift >= 0; shift -= 8) {
        for (int i = tid; i < 256; i += TOPK_THREADS) hist[i] = 0u;
        __syncthreads();
        unsigned int pfx = sh_prefix, msk = sh_mask;
        for (int j = tid; j < H; j += TOPK_THREADS) {
            unsigned int u = su[j];
            if ((u & msk) == pfx)
                atomicAdd(&hist[(u >> shift) & 255u], 1u);
        }
        __syncthreads();
        if (tid == 0) {
            int rem = sh_remaining;
            for (int b = 255; b >= 0; b--) {
                int c = (int)hist[b];
                if (c >= rem) {
                    sh_prefix |= ((unsigned int)b) << shift;
                    sh_mask   |= 0xFFu << shift;
                    sh_remaining = rem;
                    break;
                }
                rem -= c;
            }
        }
        __syncthreads();
    }

    const float v_t = key2f(sh_prefix);

    for (int j = tid; j < H; j += TOPK_THREADS) {
        float f = key2f(su[j]);
        bool core = (f > v_t + BAND_EPS);
        bool band = (fabsf(f - v_t) <= BAND_EPS);
        z[(size_t)row * H + j] = core ? f : 0.0f;
        if (core) {
            int p = atomicAdd(&ncore, 1);
            if (p < SEL_CAP) { tki[p] = j; tkv[p] = f; }
        } else if (band) {
            int p = atomicAdd(&nband, 1);
            if (p < BAND_CAP) { bidx[p] = j; bvalf[p] = f; }
        }
    }
    __syncthreads();

    const int nb = min(nband, BAND_CAP);
    for (int m = wid; m < nb; m += TOPK_THREADS / 32) {
        int j = bidx[m];
        double acc = 0.0;
        for (int d = lane; d < D; d += 32)
            acc += (double)(A[(size_t)row * D + d] - bpre[d]) *
                   (double)Wenc[(size_t)d * H + j];
#pragma unroll
        for (int o = 16; o > 0; o >>= 1)
            acc += __shfl_down_sync(0xFFFFFFFFu, acc, o);
        if (lane == 0) bvald[m] = acc;
    }
    __syncthreads();

    if (tid == 0) {
        int slots = k - min(ncore, SEL_CAP);
        if (slots < 0) slots = 0;
        if (slots > nb) slots = nb;
        for (int m = 0; m < nb; m++) bsel[m] = 0;
        int base = min(ncore, SEL_CAP);
        for (int s = 0; s < slots; s++) {
            int best = -1;
            for (int m = 0; m < nb; m++) {
                if (bsel[m]) continue;
                if (best < 0 ||
                    bvald[m] > bvald[best] ||
                    (bvald[m] == bvald[best] && bidx[m] < bidx[best]))
                    best = m;
            }
            bsel[best] = 1;
            if (base + s < SEL_CAP) { tki[base + s] = bidx[best]; tkv[base + s] = bvalf[best]; }
        }
        ntot = min(base + slots, SEL_CAP);
    }
    __syncthreads();

    for (int m = tid; m < nb; m += TOPK_THREADS)
        z[(size_t)row * H + bidx[m]] = bsel[m] ? bvalf[m] : 0.0f;
    __syncthreads();

    const int ns = ntot;
    for (int d = tid; d < D; d += TOPK_THREADS) {
        float acc = bpre[d];
        for (int i = 0; i < ns; i++)
            acc = fmaf(tkv[i], Wdec[(size_t)tki[i] * D + d], acc);
        recon[(size_t)row * D + d] = acc;
    }
}

// ---------------------------------------------------------------------------

extern "C" void kernel_launch(void* const* d_in, const int* in_sizes, int n_in,
                              void* d_out, int out_size)
{
    const float* A    = (const float*)d_in[0];
    const float* Wenc = (const float*)d_in[1];
    const float* Wdec = (const float*)d_in[2];
    const float* bpre = (const float*)d_in[3];
    const int*   kptr = (const int*)d_in[4];

    const int D = in_sizes[3];            // 768
    const int B = in_sizes[0] / D;        // 4096
    const int H = in_sizes[1] / D;        // 24576

    float* out   = (float*)d_out;
    float* recon = out;                                   // [B, D]
    float* acts  = out + (size_t)B * D;                   // [B, H]
    float* z     = out + (size_t)B * D + (size_t)B * H;   // [B, H]

    static bool attr_set = false;
    size_t tk_smem = (size_t)H * sizeof(unsigned int);
    if (!attr_set) {
        cudaFuncSetAttribute(encode_gemm_mma,
                             cudaFuncAttributeMaxDynamicSharedMemorySize,
                             GEMM_SMEM);
        cudaFuncSetAttribute(topk_decode_kernel,
                             cudaFuncAttributeMaxDynamicSharedMemorySize,
                             (int)tk_smem);
        attr_set = true;
    }

    dim3 g1(B / BM, H / BN);   // x = m-tiles fastest -> wave shares W in L2
    encode_gemm_mma<<<g1, 256, GEMM_SMEM>>>(A, Wenc, bpre, acts, D, H);

    topk_decode_kernel<<<B, TOPK_THREADS, tk_smem>>>(acts, A, Wenc, Wdec, bpre,
                                                     kptr, z, recon, H, D);
}

// round 6
// speedup vs baseline: 1.9806x; 1.9806x over previous
#include <cuda_runtime.h>
#include <cstdint>

// ---------------------------------------------------------------------------
// TopK AutoEncoder: recon = (topk(A @ W_enc)) @ W_dec + b_pre
// Outputs (tuple order): recon [B,D], acts [B,H], z [B,H]
// B=4096, D=768, H=24576, k=32
// Encode GEMM: mma.sync m16n8k16 bf16, 3x split (hh+hl+lh), split done ONCE at
// smem-store time (packed bf16x2 operands). ~3e-6 acts accuracy.
// Top-k: radix select + fp64 boundary-band refinement (exact selection).
// ---------------------------------------------------------------------------

// round-to-nearest-even bf16, returned as fp32 bit pattern (low 16 bits zero)
__device__ __forceinline__ uint32_t bf16hi_bits(float x) {
    uint32_t u = __float_as_uint(x);
    return (u + 0x7FFFu + ((u >> 16) & 1u)) & 0xFFFF0000u;
}
// split (x0,x1) -> hi pair (packed bf16x2, low half = x0), lo pair likewise
__device__ __forceinline__ void split_pair(float x0, float x1,
                                           uint32_t& hi, uint32_t& lo) {
    uint32_t h0 = bf16hi_bits(x0), h1 = bf16hi_bits(x1);
    hi = __byte_perm(h0, h1, 0x7632);
    float l0 = x0 - __uint_as_float(h0);
    float l1 = x1 - __uint_as_float(h1);
    asm("cvt.rn.bf16x2.f32 %0, %1, %2;" : "=r"(lo) : "f"(l1), "f"(l0));
}
__device__ __forceinline__ void mma16(float* c, const uint32_t* a, const uint32_t* b) {
    asm volatile(
        "mma.sync.aligned.m16n8k16.row.col.f32.bf16.bf16.f32 "
        "{%0,%1,%2,%3}, {%4,%5,%6,%7}, {%8,%9}, {%0,%1,%2,%3};"
        : "+f"(c[0]), "+f"(c[1]), "+f"(c[2]), "+f"(c[3])
        : "r"(a[0]), "r"(a[1]), "r"(a[2]), "r"(a[3]), "r"(b[0]), "r"(b[1]));
}

// ===================== Kernel 1: encode GEMM (bf16x3) =======================
// Block tile 128(m) x 256(n), Kc=16 per chunk, 48 chunks. 8 warps 2(m)x4(n),
// warp tile 64x64 -> 4 mt x 8 nt of m16n8k16, 3 MMAs each (hh, hl, lh).
// smem: pair-words [row][j] (j = k/2), pitch 12 words (8 used + 4 pad).
#define BM 128
#define BN 256
#define NCH 48
#define AP 12
#define WP 12
#define AS_W (128 * AP)   /* 1536 words */
#define WS_W (256 * WP)   /* 3072 words */
#define GEMM_SMEM ((4 * AS_W + 4 * WS_W) * 4)   /* 73728 B */

__global__ void __launch_bounds__(256, 1)
encode_gemm_bf16(const float* __restrict__ A,
                 const float* __restrict__ W,
                 const float* __restrict__ bpre,
                 float* __restrict__ acts,
                 int D, int H)
{
    extern __shared__ uint32_t sm[];
    uint32_t* AhS[2] = { sm,            sm + 2 * AS_W };
    uint32_t* AlS[2] = { sm + AS_W,     sm + 3 * AS_W };
    uint32_t* WhS[2] = { sm + 4 * AS_W,            sm + 4 * AS_W + 2 * WS_W };
    uint32_t* WlS[2] = { sm + 4 * AS_W + WS_W,     sm + 4 * AS_W + 3 * WS_W };

    const int tid = threadIdx.x;
    const int w = tid >> 5;
    const int lane = tid & 31;
    const int lr = lane >> 2;
    const int lc = lane & 3;
    const int wm = w >> 2;
    const int wn = w & 3;
    const int m0 = blockIdx.x * BM;
    const int n0 = blockIdx.y * BN;

    float C[4][8][4];
#pragma unroll
    for (int mt = 0; mt < 4; mt++)
#pragma unroll
        for (int nt = 0; nt < 8; nt++)
#pragma unroll
            for (int r = 0; r < 4; r++) C[mt][nt][r] = 0.0f;

    // raw-chunk registers: A 2x float4, W 16 floats
    float4 aw[2];
    float ww[16];

    // ---- load chunk 0 into regs
    {
#pragma unroll
        for (int i = 0; i < 2; i++) {
            int idx = tid + 256 * i;
            int m = idx >> 2, kq = (idx & 3) * 4;
            aw[i] = *(const float4*)(A + (size_t)(m0 + m) * D + kq);
        }
        const float* wp = W + n0 + tid;
#pragma unroll
        for (int r = 0; r < 16; r++) ww[r] = __ldg(wp + (size_t)r * H);
    }

#pragma unroll 1
    for (int c = 0; c < NCH; c++) {
        const int buf = c & 1;
        const int k0 = c * 16;
        const int k0n = k0 + 16;
        const bool more = (c + 1 < NCH);

        // ---- split + STS chunk c from regs
        {
            uint32_t* Ah = AhS[buf];
            uint32_t* Al = AlS[buf];
#pragma unroll
            for (int i = 0; i < 2; i++) {
                int idx = tid + 256 * i;
                int m = idx >> 2, kq = (idx & 3) * 4;
                float4 av = aw[i];
                float4 bv = *(const float4*)(bpre + k0 + kq);
                uint32_t h0, l0, h1, l1;
                split_pair(av.x - bv.x, av.y - bv.y, h0, l0);
                split_pair(av.z - bv.z, av.w - bv.w, h1, l1);
                int j = kq >> 1;
                *(uint2*)&Ah[m * AP + j] = make_uint2(h0, h1);
                *(uint2*)&Al[m * AP + j] = make_uint2(l0, l1);
            }
            uint32_t ph[8], pl[8];
#pragma unroll
            for (int j = 0; j < 8; j++)
                split_pair(ww[2 * j], ww[2 * j + 1], ph[j], pl[j]);
            uint32_t* Wh = WhS[buf];
            uint32_t* Wl = WlS[buf];
            *(uint4*)&Wh[tid * WP + 0] = make_uint4(ph[0], ph[1], ph[2], ph[3]);
            *(uint4*)&Wh[tid * WP + 4] = make_uint4(ph[4], ph[5], ph[6], ph[7]);
            *(uint4*)&Wl[tid * WP + 0] = make_uint4(pl[0], pl[1], pl[2], pl[3]);
            *(uint4*)&Wl[tid * WP + 4] = make_uint4(pl[4], pl[5], pl[6], pl[7]);
        }
        __syncthreads();

        // ---- prefetch chunk c+1 into regs (hidden under MMAs below)
        if (more) {
#pragma unroll
            for (int i = 0; i < 2; i++) {
                int idx = tid + 256 * i;
                int m = idx >> 2, kq = (idx & 3) * 4;
                aw[i] = *(const float4*)(A + (size_t)(m0 + m) * D + k0n + kq);
            }
            const float* wp = W + (size_t)k0n * H + n0 + tid;
#pragma unroll
            for (int r = 0; r < 16; r++) ww[r] = __ldg(wp + (size_t)r * H);
        }

        // ---- compute chunk c: cache B frags, sweep mt
        {
            const uint32_t* Ah = AhS[buf];
            const uint32_t* Al = AlS[buf];
            const uint32_t* Wh = WhS[buf];
            const uint32_t* Wl = WlS[buf];
            uint32_t Bh[8][2], Bl[8][2];
#pragma unroll
            for (int nt = 0; nt < 8; nt++) {
                int n = wn * 64 + nt * 8 + lr;
                Bh[nt][0] = Wh[n * WP + lc];
                Bh[nt][1] = Wh[n * WP + lc + 4];
                Bl[nt][0] = Wl[n * WP + lc];
                Bl[nt][1] = Wl[n * WP + lc + 4];
            }
#pragma unroll
            for (int mt = 0; mt < 4; mt++) {
                int m = wm * 64 + mt * 16 + lr;
                uint32_t Af[4] = { Ah[m * AP + lc],       Ah[(m + 8) * AP + lc],
                                   Ah[m * AP + lc + 4],   Ah[(m + 8) * AP + lc + 4] };
                uint32_t Afl[4] = { Al[m * AP + lc],      Al[(m + 8) * AP + lc],
                                    Al[m * AP + lc + 4],  Al[(m + 8) * AP + lc + 4] };
#pragma unroll
                for (int nt = 0; nt < 8; nt++) {
                    mma16(C[mt][nt], Af, Bh[nt]);    // hh
                    mma16(C[mt][nt], Af, Bl[nt]);    // hl
                    mma16(C[mt][nt], Afl, Bh[nt]);   // lh
                }
            }
        }
    }

    // ---- epilogue
#pragma unroll
    for (int mt = 0; mt < 4; mt++) {
        const int r0 = m0 + wm * 64 + mt * 16 + lr;
#pragma unroll
        for (int nt = 0; nt < 8; nt++) {
            const int cc = n0 + wn * 64 + nt * 8 + 2 * lc;
            *(float2*)(acts + (size_t)r0 * H + cc) =
                make_float2(C[mt][nt][0], C[mt][nt][1]);
            *(float2*)(acts + (size_t)(r0 + 8) * H + cc) =
                make_float2(C[mt][nt][2], C[mt][nt][3]);
        }
    }
}

// ============ Kernel 2: top-k (fp64-refined boundary) + z + decode ==========
__device__ __forceinline__ unsigned int f2key(float f) {
    unsigned int u = __float_as_uint(f);
    return (u & 0x80000000u) ? ~u : (u | 0x80000000u);
}
__device__ __forceinline__ float key2f(unsigned int u) {
    unsigned int b = (u & 0x80000000u) ? (u ^ 0x80000000u) : ~u;
    return __uint_as_float(b);
}

#define TOPK_THREADS 256
#define SEL_CAP 64
#define BAND_CAP 64
#define BAND_EPS 2e-3f

__global__ void __launch_bounds__(TOPK_THREADS)
topk_decode_kernel(const float* __restrict__ acts,
                   const float* __restrict__ A,
                   const float* __restrict__ Wenc,
                   const float* __restrict__ Wdec,
                   const float* __restrict__ bpre,
                   const int* __restrict__ kptr,
                   float* __restrict__ z,
                   float* __restrict__ recon,
                   int H, int D)
{
    extern __shared__ unsigned int su[];   // H keys
    __shared__ unsigned int hist[256];
    __shared__ unsigned int sh_prefix, sh_mask;
    __shared__ int sh_remaining;
    __shared__ int ncore, nband;
    __shared__ int   tki[SEL_CAP];
    __shared__ float tkv[SEL_CAP];
    __shared__ int    bidx[BAND_CAP];
    __shared__ float  bvalf[BAND_CAP];
    __shared__ double bvald[BAND_CAP];
    __shared__ unsigned char bsel[BAND_CAP];
    __shared__ int ntot;

    const int row = blockIdx.x;
    const int tid = threadIdx.x;
    const int lane = tid & 31;
    const int wid = tid >> 5;
    const int k = *kptr;
    const float* arow = acts + (size_t)row * H;

    for (int j = tid; j < H; j += TOPK_THREADS)
        su[j] = f2key(arow[j]);

    if (tid == 0) {
        sh_prefix = 0u; sh_mask = 0u; sh_remaining = k;
        ncore = 0; nband = 0; ntot = 0;
    }
    __syncthreads();

#pragma unroll
    for (int shift = 24; shift >= 0; shift -= 8) {
        for (int i = tid; i < 256; i += TOPK_THREADS) hist[i] = 0u;
        __syncthreads();
        unsigned int pfx = sh_prefix, msk = sh_mask;
        for (int j = tid; j < H; j += TOPK_THREADS) {
            unsigned int u = su[j];
            if ((u & msk) == pfx)
                atomicAdd(&hist[(u >> shift) & 255u], 1u);
        }
        __syncthreads();
        if (tid == 0) {
            int rem = sh_remaining;
            for (int b = 255; b >= 0; b--) {
                int c = (int)hist[b];
                if (c >= rem) {
                    sh_prefix |= ((unsigned int)b) << shift;
                    sh_mask   |= 0xFFu << shift;
                    sh_remaining = rem;
                    break;
                }
                rem -= c;
            }
        }
        __syncthreads();
    }

    const float v_t = key2f(sh_prefix);

    for (int j = tid; j < H; j += TOPK_THREADS) {
        float f = key2f(su[j]);
        bool core = (f > v_t + BAND_EPS);
        bool band = (fabsf(f - v_t) <= BAND_EPS);
        z[(size_t)row * H + j] = core ? f : 0.0f;
        if (core) {
            int p = atomicAdd(&ncore, 1);
            if (p < SEL_CAP) { tki[p] = j; tkv[p] = f; }
        } else if (band) {
            int p = atomicAdd(&nband, 1);
            if (p < BAND_CAP) { bidx[p] = j; bvalf[p] = f; }
        }
    }
    __syncthreads();

    const int nb = min(nband, BAND_CAP);
    for (int m = wid; m < nb; m += TOPK_THREADS / 32) {
        int j = bidx[m];
        double acc = 0.0;
        for (int d = lane; d < D; d += 32)
            acc += (double)(A[(size_t)row * D + d] - bpre[d]) *
                   (double)Wenc[(size_t)d * H + j];
#pragma unroll
        for (int o = 16; o > 0; o >>= 1)
            acc += __shfl_down_sync(0xFFFFFFFFu, acc, o);
        if (lane == 0) bvald[m] = acc;
    }
    __syncthreads();

    if (tid == 0) {
        int slots = k - min(ncore, SEL_CAP);
        if (slots < 0) slots = 0;
        if (slots > nb) slots = nb;
        for (int m = 0; m < nb; m++) bsel[m] = 0;
        int base = min(ncore, SEL_CAP);
        for (int s = 0; s < slots; s++) {
            int best = -1;
            for (int m = 0; m < nb; m++) {
                if (bsel[m]) continue;
                if (best < 0 ||
                    bvald[m] > bvald[best] ||
                    (bvald[m] == bvald[best] && bidx[m] < bidx[best]))
                    best = m;
            }
            bsel[best] = 1;
            if (base + s < SEL_CAP) { tki[base + s] = bidx[best]; tkv[base + s] = bvalf[best]; }
        }
        ntot = min(base + slots, SEL_CAP);
    }
    __syncthreads();

    for (int m = tid; m < nb; m += TOPK_THREADS)
        z[(size_t)row * H + bidx[m]] = bsel[m] ? bvalf[m] : 0.0f;
    __syncthreads();

    const int ns = ntot;
    for (int d = tid; d < D; d += TOPK_THREADS) {
        float acc = bpre[d];
        for (int i = 0; i < ns; i++)
            acc = fmaf(tkv[i], Wdec[(size_t)tki[i] * D + d], acc);
        recon[(size_t)row * D + d] = acc;
    }
}

// ---------------------------------------------------------------------------

extern "C" void kernel_launch(void* const* d_in, const int* in_sizes, int n_in,
                              void* d_out, int out_size)
{
    const float* A    = (const float*)d_in[0];
    const float* Wenc = (const float*)d_in[1];
    const float* Wdec = (const float*)d_in[2];
    const float* bpre = (const float*)d_in[3];
    const int*   kptr = (const int*)d_in[4];

    const int D = in_sizes[3];            // 768
    const int B = in_sizes[0] / D;        // 4096
    const int H = in_sizes[1] / D;        // 24576

    float* out   = (float*)d_out;
    float* recon = out;                                   // [B, D]
    float* acts  = out + (size_t)B * D;                   // [B, H]
    float* z     = out + (size_t)B * D + (size_t)B * H;   // [B, H]

    static bool attr_set = false;
    size_t tk_smem = (size_t)H * sizeof(unsigned int);
    if (!attr_set) {
        cudaFuncSetAttribute(encode_gemm_bf16,
                             cudaFuncAttributeMaxDynamicSharedMemorySize,
                             GEMM_SMEM);
        cudaFuncSetAttribute(topk_decode_kernel,
                             cudaFuncAttributeMaxDynamicSharedMemorySize,
                             (int)tk_smem);
        attr_set = true;
    }

    dim3 g1(B / BM, H / BN);   // x = m-tiles fastest -> wave shares W in L2
    encode_gemm_bf16<<<g1, 256, GEMM_SMEM>>>(A, Wenc, bpre, acts, D, H);

    topk_decode_kernel<<<B, TOPK_THREADS, tk_smem>>>(acts, A, Wenc, Wdec, bpre,
                                                     kptr, z, recon, H, D);
}

// round 8
// speedup vs baseline: 2.0212x; 1.0205x over previous
#include <cuda_runtime.h>
#include <cstdint>

// ---------------------------------------------------------------------------
// TopK AutoEncoder: recon = (topk(A @ W_enc)) @ W_dec + b_pre
// Outputs (tuple order): recon [B,D], acts [B,H], z [B,H]
// B=4096, D=768, H=24576, k=32
// Encode GEMM: mma.sync m16n8k16 bf16, 3x split (hh+hl+lh), split at STS time.
// R7: phase-major MMA order -> no same-accumulator dependency chains.
// Top-k: radix select + fp64 boundary-band refinement (exact selection).
// ---------------------------------------------------------------------------

__device__ __forceinline__ uint32_t bf16hi_bits(float x) {
    uint32_t u = __float_as_uint(x);
    return (u + 0x7FFFu + ((u >> 16) & 1u)) & 0xFFFF0000u;
}
__device__ __forceinline__ void split_pair(float x0, float x1,
                                           uint32_t& hi, uint32_t& lo) {
    uint32_t h0 = bf16hi_bits(x0), h1 = bf16hi_bits(x1);
    hi = __byte_perm(h0, h1, 0x7632);
    float l0 = x0 - __uint_as_float(h0);
    float l1 = x1 - __uint_as_float(h1);
    asm("cvt.rn.bf16x2.f32 %0, %1, %2;" : "=r"(lo) : "f"(l1), "f"(l0));
}
__device__ __forceinline__ void mma16(float* c, const uint32_t* a, const uint32_t* b) {
    asm volatile(
        "mma.sync.aligned.m16n8k16.row.col.f32.bf16.bf16.f32 "
        "{%0,%1,%2,%3}, {%4,%5,%6,%7}, {%8,%9}, {%0,%1,%2,%3};"
        : "+f"(c[0]), "+f"(c[1]), "+f"(c[2]), "+f"(c[3])
        : "r"(a[0]), "r"(a[1]), "r"(a[2]), "r"(a[3]), "r"(b[0]), "r"(b[1]));
}

// ===================== Kernel 1: encode GEMM (bf16x3) =======================
#define BM 128
#define BN 256
#define NCH 48
#define AP 12
#define WP 12
#define AS_W (128 * AP)
#define WS_W (256 * WP)
#define GEMM_SMEM ((4 * AS_W + 4 * WS_W) * 4)

__global__ void __launch_bounds__(256, 1)
encode_gemm_bf16(const float* __restrict__ A,
                 const float* __restrict__ W,
                 const float* __restrict__ bpre,
                 float* __restrict__ acts,
                 int D, int H)
{
    extern __shared__ uint32_t sm[];
    uint32_t* AhS[2] = { sm,            sm + 2 * AS_W };
    uint32_t* AlS[2] = { sm + AS_W,     sm + 3 * AS_W };
    uint32_t* WhS[2] = { sm + 4 * AS_W,            sm + 4 * AS_W + 2 * WS_W };
    uint32_t* WlS[2] = { sm + 4 * AS_W + WS_W,     sm + 4 * AS_W + 3 * WS_W };

    const int tid = threadIdx.x;
    const int w = tid >> 5;
    const int lane = tid & 31;
    const int lr = lane >> 2;
    const int lc = lane & 3;
    const int wm = w >> 2;
    const int wn = w & 3;
    const int m0 = blockIdx.x * BM;
    const int n0 = blockIdx.y * BN;

    float C[4][8][4];
#pragma unroll
    for (int mt = 0; mt < 4; mt++)
#pragma unroll
        for (int nt = 0; nt < 8; nt++)
#pragma unroll
            for (int r = 0; r < 4; r++) C[mt][nt][r] = 0.0f;

    float4 aw[2];
    float ww[16];

    // ---- load chunk 0 into regs
    {
#pragma unroll
        for (int i = 0; i < 2; i++) {
            int idx = tid + 256 * i;
            int m = idx >> 2, kq = (idx & 3) * 4;
            aw[i] = *(const float4*)(A + (size_t)(m0 + m) * D + kq);
        }
        const float* wp = W + n0 + tid;
#pragma unroll
        for (int r = 0; r < 16; r++) ww[r] = __ldg(wp + (size_t)r * H);
    }

#pragma unroll 1
    for (int c = 0; c < NCH; c++) {
        const int buf = c & 1;
        const int k0 = c * 16;
        const int k0n = k0 + 16;
        const bool more = (c + 1 < NCH);

        // ---- split + STS chunk c from regs
        {
            uint32_t* Ah = AhS[buf];
            uint32_t* Al = AlS[buf];
#pragma unroll
            for (int i = 0; i < 2; i++) {
                int idx = tid + 256 * i;
                int m = idx >> 2, kq = (idx & 3) * 4;
                float4 av = aw[i];
                float4 bv = *(const float4*)(bpre + k0 + kq);
                uint32_t h0, l0, h1, l1;
                split_pair(av.x - bv.x, av.y - bv.y, h0, l0);
                split_pair(av.z - bv.z, av.w - bv.w, h1, l1);
                int j = kq >> 1;
                *(uint2*)&Ah[m * AP + j] = make_uint2(h0, h1);
                *(uint2*)&Al[m * AP + j] = make_uint2(l0, l1);
            }
            uint32_t ph[8], pl[8];
#pragma unroll
            for (int j = 0; j < 8; j++)
                split_pair(ww[2 * j], ww[2 * j + 1], ph[j], pl[j]);
            uint32_t* Wh = WhS[buf];
            uint32_t* Wl = WlS[buf];
            *(uint4*)&Wh[tid * WP + 0] = make_uint4(ph[0], ph[1], ph[2], ph[3]);
            *(uint4*)&Wh[tid * WP + 4] = make_uint4(ph[4], ph[5], ph[6], ph[7]);
            *(uint4*)&Wl[tid * WP + 0] = make_uint4(pl[0], pl[1], pl[2], pl[3]);
            *(uint4*)&Wl[tid * WP + 4] = make_uint4(pl[4], pl[5], pl[6], pl[7]);
        }
        __syncthreads();

        // ---- prefetch chunk c+1 into regs (hidden under MMAs below)
        if (more) {
#pragma unroll
            for (int i = 0; i < 2; i++) {
                int idx = tid + 256 * i;
                int m = idx >> 2, kq = (idx & 3) * 4;
                aw[i] = *(const float4*)(A + (size_t)(m0 + m) * D + k0n + kq);
            }
            const float* wp = W + (size_t)k0n * H + n0 + tid;
#pragma unroll
            for (int r = 0; r < 16; r++) ww[r] = __ldg(wp + (size_t)r * H);
        }

        // ---- compute chunk c: phase-major order (no dependent MMA chains)
        {
            const uint32_t* Ah = AhS[buf];
            const uint32_t* Al = AlS[buf];
            const uint32_t* Wh = WhS[buf];
            const uint32_t* Wl = WlS[buf];
            uint32_t Bh[8][2], Bl[8][2];
#pragma unroll
            for (int nt = 0; nt < 8; nt++) {
                int n = wn * 64 + nt * 8 + lr;
                Bh[nt][0] = Wh[n * WP + lc];
                Bh[nt][1] = Wh[n * WP + lc + 4];
                Bl[nt][0] = Wl[n * WP + lc];
                Bl[nt][1] = Wl[n * WP + lc + 4];
            }
#pragma unroll
            for (int mt = 0; mt < 4; mt++) {
                int m = wm * 64 + mt * 16 + lr;
                uint32_t Af[4]  = { Ah[m * AP + lc],      Ah[(m + 8) * AP + lc],
                                    Ah[m * AP + lc + 4],  Ah[(m + 8) * AP + lc + 4] };
                uint32_t Afl[4] = { Al[m * AP + lc],      Al[(m + 8) * AP + lc],
                                    Al[m * AP + lc + 4],  Al[(m + 8) * AP + lc + 4] };
                // phase hh: 8 independent accumulators
#pragma unroll
                for (int nt = 0; nt < 8; nt++) mma16(C[mt][nt], Af, Bh[nt]);
                // phase hl
#pragma unroll
                for (int nt = 0; nt < 8; nt++) mma16(C[mt][nt], Af, Bl[nt]);
                // phase lh
#pragma unroll
                for (int nt = 0; nt < 8; nt++) mma16(C[mt][nt], Afl, Bh[nt]);
            }
        }
    }

    // ---- epilogue
#pragma unroll
    for (int mt = 0; mt < 4; mt++) {
        const int r0 = m0 + wm * 64 + mt * 16 + lr;
#pragma unroll
        for (int nt = 0; nt < 8; nt++) {
            const int cc = n0 + wn * 64 + nt * 8 + 2 * lc;
            *(float2*)(acts + (size_t)r0 * H + cc) =
                make_float2(C[mt][nt][0], C[mt][nt][1]);
            *(float2*)(acts + (size_t)(r0 + 8) * H + cc) =
                make_float2(C[mt][nt][2], C[mt][nt][3]);
        }
    }
}

// ============ Kernel 2: top-k (fp64-refined boundary) + z + decode ==========
__device__ __forceinline__ unsigned int f2key(float f) {
    unsigned int u = __float_as_uint(f);
    return (u & 0x80000000u) ? ~u : (u | 0x80000000u);
}
__device__ __forceinline__ float key2f(unsigned int u) {
    unsigned int b = (u & 0x80000000u) ? (u ^ 0x80000000u) : ~u;
    return __uint_as_float(b);
}

#define TOPK_THREADS 256
#define SEL_CAP 64
#define BAND_CAP 64
#define BAND_EPS 2e-3f

__global__ void __launch_bounds__(TOPK_THREADS)
topk_decode_kernel(const float* __restrict__ acts,
                   const float* __restrict__ A,
                   const float* __restrict__ Wenc,
                   const float* __restrict__ Wdec,
                   const float* __restrict__ bpre,
                   const int* __restrict__ kptr,
                   float* __restrict__ z,
                   float* __restrict__ recon,
                   int H, int D)
{
    extern __shared__ unsigned int su[];   // H keys
    __shared__ unsigned int hist[256];
    __shared__ unsigned int sh_prefix, sh_mask;
    __shared__ int sh_remaining;
    __shared__ int ncore, nband;
    __shared__ int   tki[SEL_CAP];
    __shared__ float tkv[SEL_CAP];
    __shared__ int    bidx[BAND_CAP];
    __shared__ float  bvalf[BAND_CAP];
    __shared__ double bvald[BAND_CAP];
    __shared__ unsigned char bsel[BAND_CAP];
    __shared__ int ntot;

    const int row = blockIdx.x;
    const int tid = threadIdx.x;
    const int lane = tid & 31;
    const int wid = tid >> 5;
    const int k = *kptr;
    const float* arow = acts + (size_t)row * H;

    for (int j = tid; j < H; j += TOPK_THREADS)
        su[j] = f2key(arow[j]);

    if (tid == 0) {
        sh_prefix = 0u; sh_mask = 0u; sh_remaining = k;
        ncore = 0; nband = 0; ntot = 0;
    }
    __syncthreads();

#pragma unroll
    for (int shift = 24; shift >= 0; shift -= 8) {
        for (int i = tid; i < 256; i += TOPK_THREADS) hist[i] = 0u;
        __syncthreads();
        unsigned int pfx = sh_prefix, msk = sh_mask;
        for (int j = tid; j < H; j += TOPK_THREADS) {
            unsigned int u = su[j];
            if ((u & msk) == pfx)
                atomicAdd(&hist[(u >> shift) & 255u], 1u);
        }
        __syncthreads();
        if (tid == 0) {
            int rem = sh_remaining;
            for (int b = 255; b >= 0; b--) {
                int c = (int)hist[b];
                if (c >= rem) {
                    sh_prefix |= ((unsigned int)b) << shift;
                    sh_mask   |= 0xFFu << shift;
                    sh_remaining = rem;
                    break;
                }
                rem -= c;
            }
        }
        __syncthreads();
    }

    const float v_t = key2f(sh_prefix);

    for (int j = tid; j < H; j += TOPK_THREADS) {
        float f = key2f(su[j]);
        bool core = (f > v_t + BAND_EPS);
        bool band = (fabsf(f - v_t) <= BAND_EPS);
        z[(size_t)row * H + j] = core ? f : 0.0f;
        if (core) {
            int p = atomicAdd(&ncore, 1);
            if (p < SEL_CAP) { tki[p] = j; tkv[p] = f; }
        } else if (band) {
            int p = atomicAdd(&nband, 1);
            if (p < BAND_CAP) { bidx[p] = j; bvalf[p] = f; }
        }
    }
    __syncthreads();

    const int nb = min(nband, BAND_CAP);
    for (int m = wid; m < nb; m += TOPK_THREADS / 32) {
        int j = bidx[m];
        double acc = 0.0;
        for (int d = lane; d < D; d += 32)
            acc += (double)(A[(size_t)row * D + d] - bpre[d]) *
                   (double)Wenc[(size_t)d * H + j];
#pragma unroll
        for (int o = 16; o > 0; o >>= 1)
            acc += __shfl_down_sync(0xFFFFFFFFu, acc, o);
        if (lane == 0) bvald[m] = acc;
    }
    __syncthreads();

    if (tid == 0) {
        int slots = k - min(ncore, SEL_CAP);
        if (slots < 0) slots = 0;
        if (slots > nb) slots = nb;
        for (int m = 0; m < nb; m++) bsel[m] = 0;
        int base = min(ncore, SEL_CAP);
        for (int s = 0; s < slots; s++) {
            int best = -1;
            for (int m = 0; m < nb; m++) {
                if (bsel[m]) continue;
                if (best < 0 ||
                    bvald[m] > bvald[best] ||
                    (bvald[m] == bvald[best] && bidx[m] < bidx[best]))
                    best = m;
            }
            bsel[best] = 1;
            if (base + s < SEL_CAP) { tki[base + s] = bidx[best]; tkv[base + s] = bvalf[best]; }
        }
        ntot = min(base + slots, SEL_CAP);
    }
    __syncthreads();

    for (int m = tid; m < nb; m += TOPK_THREADS)
        z[(size_t)row * H + bidx[m]] = bsel[m] ? bvalf[m] : 0.0f;
    __syncthreads();

    const int ns = ntot;
    for (int d = tid; d < D; d += TOPK_THREADS) {
        float acc = bpre[d];
        for (int i = 0; i < ns; i++)
            acc = fmaf(tkv[i], Wdec[(size_t)tki[i] * D + d], acc);
        recon[(size_t)row * D + d] = acc;
    }
}

// ---------------------------------------------------------------------------

extern "C" void kernel_launch(void* const* d_in, const int* in_sizes, int n_in,
                              void* d_out, int out_size)
{
    const float* A    = (const float*)d_in[0];
    const float* Wenc = (const float*)d_in[1];
    const float* Wdec = (const float*)d_in[2];
    const float* bpre = (const float*)d_in[3];
    const int*   kptr = (const int*)d_in[4];

    const int D = in_sizes[3];            // 768
    const int B = in_sizes[0] / D;        // 4096
    const int H = in_sizes[1] / D;        // 24576

    float* out   = (float*)d_out;
    float* recon = out;                                   // [B, D]
    float* acts  = out + (size_t)B * D;                   // [B, H]
    float* z     = out + (size_t)B * D + (size_t)B * H;   // [B, H]

    static bool attr_set = false;
    size_t tk_smem = (size_t)H * sizeof(unsigned int);
    if (!attr_set) {
        cudaFuncSetAttribute(encode_gemm_bf16,
                             cudaFuncAttributeMaxDynamicSharedMemorySize,
                             GEMM_SMEM);
        cudaFuncSetAttribute(topk_decode_kernel,
                             cudaFuncAttributeMaxDynamicSharedMemorySize,
                             (int)tk_smem);
        attr_set = true;
    }

    dim3 g1(B / BM, H / BN);   // x = m-tiles fastest -> wave shares W in L2
    encode_gemm_bf16<<<g1, 256, GEMM_SMEM>>>(A, Wenc, bpre, acts, D, H);

    topk_decode_kernel<<<B, TOPK_THREADS, tk_smem>>>(acts, A, Wenc, Wdec, bpre,
                                                     kptr, z, recon, H, D);
}